// round 1
// baseline (speedup 1.0000x reference)
#include <cuda_runtime.h>
#include <math.h>

// Problem constants (fixed shapes)
namespace {
constexpr int C_ = 128;   // channels
constexpr int B_ = 8;     // batch
constexpr int T_ = 128;   // time
constexpr int F_ = 512;   // freq (side)
constexpr int K_ = 64;    // latent bands
constexpr int NL = T_ * K_;   // 8192  (latent spatial per batch)
constexpr int NS = T_ * F_;   // 65536 (side spatial per batch)
}

// ---------------- scratch (device globals; no allocation allowed) ----------------
__device__ float g_lat_h[(size_t)B_ * C_ * NL];
__device__ float g_kbuf [(size_t)B_ * C_ * NL];
__device__ float g_vbuf [(size_t)B_ * C_ * NL];
__device__ float g_t1  [(size_t)B_ * 2 * C_ * NS];   // swiglu pre-activation (side & ffn)
__device__ float g_u   [(size_t)B_ * C_ * NS];       // swiglu gated intermediate
__device__ float g_qh  [(size_t)B_ * C_ * NS];       // query_h
__device__ float g_qb  [(size_t)B_ * C_ * NS];       // q projection
__device__ float g_att [(size_t)B_ * C_ * NS];       // attended
__device__ float g_invl[(size_t)B_ * NL];            // rms inv (latent)
__device__ float g_invs[(size_t)B_ * NS];            // rms inv (side / hidden)

// ---------------- packed fp32x2 helpers (Blackwell FFMA2) ----------------
typedef unsigned long long u64;
__device__ __forceinline__ u64 pk2(float x, float y) {
    u64 r; asm("mov.b64 %0,{%1,%2};" : "=l"(r) : "f"(x), "f"(y)); return r;
}
__device__ __forceinline__ void up2(u64 v, float& x, float& y) {
    asm("mov.b64 {%0,%1},%2;" : "=f"(x), "=f"(y) : "l"(v));
}
__device__ __forceinline__ void fma2(u64& c, u64 a, u64 b) {
    asm("fma.rn.f32x2 %0,%1,%2,%0;" : "+l"(c) : "l"(a), "l"(b));
}

// ---------------- rms inverse scale: inv[b,n] = rsqrt(mean_c x^2 + 1e-6) ----------------
__global__ void rmsinv_kernel(const float* __restrict__ X, float* __restrict__ inv, int N) {
    int b = blockIdx.y;
    int n = blockIdx.x * 256 + threadIdx.x;
    const float* Xb = X + (size_t)b * C_ * N;
    float s = 0.f;
#pragma unroll 8
    for (int c = 0; c < C_; c++) { float v = Xb[(size_t)c * N + n]; s = fmaf(v, v, s); }
    inv[(size_t)b * N + n] = rsqrtf(s * (1.0f / C_) + 1e-6f);
}

// ---------------- generic conv1x1 GEMM: Y[b,o,n] = epi( (sum_c W'[o,c] X[b,c,n]) * cs[b,n] + bias[o] )
// EPI: 0 = none, 1 = SiLU, 2 = + skip[b,o,n]*(*sscale), 3 = add into Y (Y += acc + bias)
template <int EPI, bool GAMMA, bool CS>
__global__ void __launch_bounds__(256) mm_kernel(
    const float* __restrict__ W, const float* __restrict__ gamma,
    const float* __restrict__ bias, const float* __restrict__ X,
    const float* __restrict__ colscale, const float* __restrict__ skip,
    const float* __restrict__ sscale, float* __restrict__ Y,
    int O, int N)
{
    __shared__ float Ws[16][68];
    __shared__ float Xs[16][68];
    const int b  = blockIdx.z;
    const int o0 = blockIdx.y * 64, n0 = blockIdx.x * 64;
    const float* Xb = X + (size_t)b * C_ * N;
    float* Yb = Y + (size_t)b * O * N;
    const int tid = threadIdx.x;
    const int ty = tid >> 4, tx = tid & 15;

    u64 acc[4][2];
#pragma unroll
    for (int r = 0; r < 4; r++) { acc[r][0] = 0ull; acc[r][1] = 0ull; }

    const int wm = tid >> 2, wq = tid & 3;   // W tile: 64 rows x 16 k, float4 per thread
    const int xk = tid >> 4, xq = tid & 15;  // X tile: 16 k x 64 n, float4 per thread

    for (int c0 = 0; c0 < C_; c0 += 16) {
        float4 wv = *(const float4*)&W[(size_t)(o0 + wm) * C_ + c0 + wq * 4];
        if (GAMMA) {
            wv.x *= gamma[c0 + wq * 4 + 0];
            wv.y *= gamma[c0 + wq * 4 + 1];
            wv.z *= gamma[c0 + wq * 4 + 2];
            wv.w *= gamma[c0 + wq * 4 + 3];
        }
        float4 xv = *(const float4*)&Xb[(size_t)(c0 + xk) * N + n0 + xq * 4];
        Ws[wq * 4 + 0][wm] = wv.x;
        Ws[wq * 4 + 1][wm] = wv.y;
        Ws[wq * 4 + 2][wm] = wv.z;
        Ws[wq * 4 + 3][wm] = wv.w;
        *(float4*)&Xs[xk][xq * 4] = xv;
        __syncthreads();
#pragma unroll
        for (int kk = 0; kk < 16; kk++) {
            float4 av = *(const float4*)&Ws[kk][ty * 4];
            float4 bv = *(const float4*)&Xs[kk][tx * 4];
            u64 b0 = pk2(bv.x, bv.y), b1 = pk2(bv.z, bv.w);
            u64 a0 = pk2(av.x, av.x); fma2(acc[0][0], a0, b0); fma2(acc[0][1], a0, b1);
            u64 a1 = pk2(av.y, av.y); fma2(acc[1][0], a1, b0); fma2(acc[1][1], a1, b1);
            u64 a2 = pk2(av.z, av.z); fma2(acc[2][0], a2, b0); fma2(acc[2][1], a2, b1);
            u64 a3 = pk2(av.w, av.w); fma2(acc[3][0], a3, b0); fma2(acc[3][1], a3, b1);
        }
        __syncthreads();
    }

    const float* csb = CS ? (colscale + (size_t)b * N) : nullptr;
    float qssv = 0.f;
    if (EPI == 2) qssv = *sscale;
    const float* skipb = (EPI == 2) ? (skip + (size_t)b * C_ * N) : nullptr;

#pragma unroll
    for (int r = 0; r < 4; r++) {
        int o = o0 + ty * 4 + r;
        float bo = bias[o];
        float v0, v1, v2, v3;
        up2(acc[r][0], v0, v1);
        up2(acc[r][1], v2, v3);
        float vv[4] = {v0, v1, v2, v3};
        float* py = &Yb[(size_t)o * N + n0 + tx * 4];
        float4 ov;
#pragma unroll
        for (int j = 0; j < 4; j++) {
            float x = vv[j];
            if (CS) x *= csb[n0 + tx * 4 + j];
            x += bo;
            if (EPI == 1) x = x / (1.f + expf(-x));
            if (EPI == 2) x += skipb[(size_t)o * N + n0 + tx * 4 + j] * qssv;
            if (EPI == 3) x += py[j];
            (&ov.x)[j] = x;
        }
        *(float4*)py = ov;
    }
}

// ---------------- gated SiLU: u[b,c,n] = t1[b,c,n] * silu(t1[b,c+C,n]) ----------------
__global__ void glu_kernel(const float* __restrict__ T1, float* __restrict__ U, int N) {
    int b = blockIdx.z, c = blockIdx.y;
    int n = blockIdx.x * 256 + threadIdx.x;
    size_t base = (size_t)b * 2 * C_ * N;
    float a = T1[base + (size_t)c * N + n];
    float g = T1[base + (size_t)(c + C_) * N + n];
    U[((size_t)b * C_ + c) * N + n] = a * (g / (1.f + expf(-g)));
}

// ---------------- per-frame cross attention: one block per (b,t) ----------------
// smem: ks[128][64], vst[64][132] (V transposed, padded), qs[128][64], pst[64][68]
__global__ void __launch_bounds__(256) attn_kernel(
    const float* __restrict__ Q, const float* __restrict__ Kp, const float* __restrict__ Vp,
    const float* __restrict__ basis, const float* __restrict__ p_ss, const float* __restrict__ p_ps,
    float* __restrict__ Att)
{
    extern __shared__ float sm[];
    float* ks  = sm;                   // [128][64]
    float* vst = ks + 128 * 64;        // [64][132]  vst[k][c]
    float* qs  = vst + 64 * 132;       // [128][64]
    float* pst = qs + 128 * 64;        // [64][68]   pst[k][f_local]
    const int t = blockIdx.x, b = blockIdx.y;
    const int tid = threadIdx.x;
    const int ty = tid >> 4, tx = tid & 15;
    const float ss = *p_ss, prs = *p_ps;

    for (int idx = tid; idx < C_ * K_; idx += 256) {
        int c = idx >> 6, kk = idx & 63;
        size_t g = (((size_t)b * C_ + c) * T_ + t) * K_ + kk;
        ks[c * 64 + kk]   = Kp[g];
        vst[kk * 132 + c] = Vp[g];
    }
    __syncthreads();

    for (int f0 = 0; f0 < F_; f0 += 64) {
        for (int idx = tid; idx < C_ * 64; idx += 256) {
            int c = idx >> 6, fl = idx & 63;
            qs[c * 64 + fl] = Q[(((size_t)b * C_ + c) * T_ + t) * F_ + f0 + fl];
        }
        __syncthreads();

        // S[f=ty*4+r][k=tx*4+j] = sum_c qs[c][f] * ks[c][k]
        u64 acc[4][2];
#pragma unroll
        for (int r = 0; r < 4; r++) { acc[r][0] = 0ull; acc[r][1] = 0ull; }
#pragma unroll 8
        for (int c = 0; c < C_; c++) {
            float4 av = *(const float4*)&qs[c * 64 + ty * 4];
            float4 bv = *(const float4*)&ks[c * 64 + tx * 4];
            u64 b0 = pk2(bv.x, bv.y), b1 = pk2(bv.z, bv.w);
            u64 a0 = pk2(av.x, av.x); fma2(acc[0][0], a0, b0); fma2(acc[0][1], a0, b1);
            u64 a1 = pk2(av.y, av.y); fma2(acc[1][0], a1, b0); fma2(acc[1][1], a1, b1);
            u64 a2 = pk2(av.z, av.z); fma2(acc[2][0], a2, b0); fma2(acc[2][1], a2, b1);
            u64 a3 = pk2(av.w, av.w); fma2(acc[3][0], a3, b0); fma2(acc[3][1], a3, b1);
        }

        // scale + band prior + softmax over k (row spans tx group of 16 threads)
#pragma unroll
        for (int r = 0; r < 4; r++) {
            float s0, s1, s2, s3;
            up2(acc[r][0], s0, s1);
            up2(acc[r][1], s2, s3);
            int f = f0 + ty * 4 + r;
            s0 = fmaf(s0, ss, basis[(tx * 4 + 0) * F_ + f] * prs);
            s1 = fmaf(s1, ss, basis[(tx * 4 + 1) * F_ + f] * prs);
            s2 = fmaf(s2, ss, basis[(tx * 4 + 2) * F_ + f] * prs);
            s3 = fmaf(s3, ss, basis[(tx * 4 + 3) * F_ + f] * prs);
            float m = fmaxf(fmaxf(s0, s1), fmaxf(s2, s3));
            m = fmaxf(m, __shfl_xor_sync(0xffffffffu, m, 1));
            m = fmaxf(m, __shfl_xor_sync(0xffffffffu, m, 2));
            m = fmaxf(m, __shfl_xor_sync(0xffffffffu, m, 4));
            m = fmaxf(m, __shfl_xor_sync(0xffffffffu, m, 8));
            float e0 = __expf(s0 - m), e1 = __expf(s1 - m);
            float e2 = __expf(s2 - m), e3 = __expf(s3 - m);
            float sum = (e0 + e1) + (e2 + e3);
            sum += __shfl_xor_sync(0xffffffffu, sum, 1);
            sum += __shfl_xor_sync(0xffffffffu, sum, 2);
            sum += __shfl_xor_sync(0xffffffffu, sum, 4);
            sum += __shfl_xor_sync(0xffffffffu, sum, 8);
            float rs = 1.f / sum;
            int fl = ty * 4 + r;
            pst[(tx * 4 + 0) * 68 + fl] = e0 * rs;
            pst[(tx * 4 + 1) * 68 + fl] = e1 * rs;
            pst[(tx * 4 + 2) * 68 + fl] = e2 * rs;
            pst[(tx * 4 + 3) * 68 + fl] = e3 * rs;
        }
        __syncthreads();

        // att[c=ty*8+r][fl=tx*4+j] = sum_k vst[k][c] * pst[k][fl]
        u64 acc2[8][2];
#pragma unroll
        for (int r = 0; r < 8; r++) { acc2[r][0] = 0ull; acc2[r][1] = 0ull; }
#pragma unroll 4
        for (int kk = 0; kk < K_; kk++) {
            float4 bv = *(const float4*)&pst[kk * 68 + tx * 4];
            u64 b0 = pk2(bv.x, bv.y), b1 = pk2(bv.z, bv.w);
            const float* vr = &vst[kk * 132 + ty * 8];
#pragma unroll
            for (int r = 0; r < 8; r++) {
                u64 ar = pk2(vr[r], vr[r]);
                fma2(acc2[r][0], ar, b0);
                fma2(acc2[r][1], ar, b1);
            }
        }
#pragma unroll
        for (int r = 0; r < 8; r++) {
            int c = ty * 8 + r;
            float v0, v1, v2, v3;
            up2(acc2[r][0], v0, v1);
            up2(acc2[r][1], v2, v3);
            *(float4*)&Att[(((size_t)b * C_ + c) * T_ + t) * F_ + f0 + tx * 4] =
                make_float4(v0, v1, v2, v3);
        }
        __syncthreads();
    }
}

// ---------------- launch ----------------
extern "C" void kernel_launch(void* const* d_in, const int* in_sizes, int n_in,
                              void* d_out, int out_size)
{
    const float* latent     = (const float*)d_in[0];
    const float* side       = (const float*)d_in[1];
    const float* basis      = (const float*)d_in[2];
    const float* lp_gamma   = (const float*)d_in[3];
    const float* lp_w       = (const float*)d_in[4];
    const float* lp_b       = (const float*)d_in[5];
    const float* qn_gamma   = (const float*)d_in[6];
    const float* qmlp_in_w  = (const float*)d_in[7];
    const float* qmlp_in_b  = (const float*)d_in[8];
    const float* qmlp_out_w = (const float*)d_in[9];
    const float* qmlp_out_b = (const float*)d_in[10];
    const float* q_w        = (const float*)d_in[11];
    const float* q_b        = (const float*)d_in[12];
    const float* k_w        = (const float*)d_in[13];
    const float* k_b        = (const float*)d_in[14];
    const float* v_w        = (const float*)d_in[15];
    const float* v_b        = (const float*)d_in[16];
    const float* o_w        = (const float*)d_in[17];
    const float* o_b        = (const float*)d_in[18];
    const float* ffn_gamma  = (const float*)d_in[19];
    const float* ffn_in_w   = (const float*)d_in[20];
    const float* ffn_in_b   = (const float*)d_in[21];
    const float* ffn_out_w  = (const float*)d_in[22];
    const float* ffn_out_b  = (const float*)d_in[23];
    const float* score_scale= (const float*)d_in[24];
    const float* prior_scale= (const float*)d_in[25];
    const float* qss        = (const float*)d_in[26];
    float* out = (float*)d_out;

    void* p;
    cudaGetSymbolAddress(&p, g_lat_h); float* lat_h = (float*)p;
    cudaGetSymbolAddress(&p, g_kbuf);  float* kb    = (float*)p;
    cudaGetSymbolAddress(&p, g_vbuf);  float* vb    = (float*)p;
    cudaGetSymbolAddress(&p, g_t1);    float* t1    = (float*)p;
    cudaGetSymbolAddress(&p, g_u);     float* u     = (float*)p;
    cudaGetSymbolAddress(&p, g_qh);    float* qh    = (float*)p;
    cudaGetSymbolAddress(&p, g_qb);    float* qb    = (float*)p;
    cudaGetSymbolAddress(&p, g_att);   float* att   = (float*)p;
    cudaGetSymbolAddress(&p, g_invl);  float* invl  = (float*)p;
    cudaGetSymbolAddress(&p, g_invs);  float* invs  = (float*)p;

    // ---- latent path: latent_h = silu(lp_w@rmsnorm(latent)+lp_b); k,v projections
    rmsinv_kernel<<<dim3(NL / 256, B_), 256>>>(latent, invl, NL);
    mm_kernel<1, true, true><<<dim3(NL / 64, 2, B_), 256>>>(
        lp_w, lp_gamma, lp_b, latent, invl, nullptr, nullptr, lat_h, C_, NL);
    mm_kernel<0, false, false><<<dim3(NL / 64, 2, B_), 256>>>(
        k_w, nullptr, k_b, lat_h, nullptr, nullptr, nullptr, kb, C_, NL);
    mm_kernel<0, false, false><<<dim3(NL / 64, 2, B_), 256>>>(
        v_w, nullptr, v_b, lat_h, nullptr, nullptr, nullptr, vb, C_, NL);

    // ---- side path: query_h = swiglu(rmsnorm(side)); q projection
    rmsinv_kernel<<<dim3(NS / 256, B_), 256>>>(side, invs, NS);
    mm_kernel<0, true, true><<<dim3(NS / 64, 4, B_), 256>>>(
        qmlp_in_w, qn_gamma, qmlp_in_b, side, invs, nullptr, nullptr, t1, 2 * C_, NS);
    glu_kernel<<<dim3(NS / 256, C_, B_), 256>>>(t1, u, NS);
    mm_kernel<0, false, false><<<dim3(NS / 64, 2, B_), 256>>>(
        qmlp_out_w, nullptr, qmlp_out_b, u, nullptr, nullptr, nullptr, qh, C_, NS);
    mm_kernel<0, false, false><<<dim3(NS / 64, 2, B_), 256>>>(
        q_w, nullptr, q_b, qh, nullptr, nullptr, nullptr, qb, C_, NS);

    // ---- attention (per-frame) -> attended
    constexpr int ATTN_SMEM = (128 * 64 + 64 * 132 + 128 * 64 + 64 * 68) * 4;  // 116736
    cudaFuncSetAttribute(attn_kernel, cudaFuncAttributeMaxDynamicSharedMemorySize, ATTN_SMEM);
    attn_kernel<<<dim3(T_, B_), 256, ATTN_SMEM>>>(qb, kb, vb, basis, score_scale, prior_scale, att);

    // ---- hidden = o_w@attended + o_b + query_h * query_skip_scale
    mm_kernel<2, false, false><<<dim3(NS / 64, 2, B_), 256>>>(
        o_w, nullptr, o_b, att, nullptr, qh, qss, out, C_, NS);

    // ---- ffn: hidden += swiglu(rmsnorm(hidden))
    rmsinv_kernel<<<dim3(NS / 256, B_), 256>>>(out, invs, NS);
    mm_kernel<0, true, true><<<dim3(NS / 64, 4, B_), 256>>>(
        ffn_in_w, ffn_gamma, ffn_in_b, out, invs, nullptr, nullptr, t1, 2 * C_, NS);
    glu_kernel<<<dim3(NS / 256, C_, B_), 256>>>(t1, u, NS);
    mm_kernel<3, false, false><<<dim3(NS / 64, 2, B_), 256>>>(
        ffn_out_w, nullptr, ffn_out_b, u, nullptr, nullptr, nullptr, out, C_, NS);
}

// round 2
// speedup vs baseline: 1.0013x; 1.0013x over previous
#include <cuda_runtime.h>
#include <math.h>

// Problem constants (fixed shapes)
namespace {
constexpr int C_ = 128;   // channels
constexpr int B_ = 8;     // batch
constexpr int T_ = 128;   // time
constexpr int F_ = 512;   // freq (side)
constexpr int K_ = 64;    // latent bands
constexpr int NL = T_ * K_;   // 8192  (latent spatial per batch)
constexpr int NS = T_ * F_;   // 65536 (side spatial per batch)
}

// ---------------- scratch (device globals; no allocation allowed) ----------------
__device__ float g_lat_h[(size_t)B_ * C_ * NL];
__device__ float g_kbuf [(size_t)B_ * C_ * NL];
__device__ float g_vbuf [(size_t)B_ * C_ * NL];
__device__ float g_t1  [(size_t)B_ * 2 * C_ * NS];   // swiglu pre-activation (side & ffn)
__device__ float g_u   [(size_t)B_ * C_ * NS];       // swiglu gated intermediate
__device__ float g_qh  [(size_t)B_ * C_ * NS];       // query_h
__device__ float g_qb  [(size_t)B_ * C_ * NS];       // q projection
__device__ float g_att [(size_t)B_ * C_ * NS];       // attended
__device__ float g_invl[(size_t)B_ * NL];            // rms inv (latent)
__device__ float g_invs[(size_t)B_ * NS];            // rms inv (side / hidden)

// ---------------- packed fp32x2 helpers (Blackwell FFMA2) ----------------
typedef unsigned long long u64;
__device__ __forceinline__ u64 pk2(float x, float y) {
    u64 r; asm("mov.b64 %0,{%1,%2};" : "=l"(r) : "f"(x), "f"(y)); return r;
}
__device__ __forceinline__ void up2(u64 v, float& x, float& y) {
    asm("mov.b64 {%0,%1},%2;" : "=f"(x), "=f"(y) : "l"(v));
}
__device__ __forceinline__ void fma2(u64& c, u64 a, u64 b) {
    asm("fma.rn.f32x2 %0,%1,%2,%0;" : "+l"(c) : "l"(a), "l"(b));
}

// ---------------- rms inverse scale: inv[b,n] = rsqrt(mean_c x^2 + 1e-6) ----------------
__global__ void rmsinv_kernel(const float* __restrict__ X, float* __restrict__ inv, int N) {
    int b = blockIdx.y;
    int n = blockIdx.x * 256 + threadIdx.x;
    const float* Xb = X + (size_t)b * C_ * N;
    float s = 0.f;
#pragma unroll 8
    for (int c = 0; c < C_; c++) { float v = Xb[(size_t)c * N + n]; s = fmaf(v, v, s); }
    inv[(size_t)b * N + n] = rsqrtf(s * (1.0f / C_) + 1e-6f);
}

// ---------------- generic conv1x1 GEMM: Y[b,o,n] = epi( (sum_c W'[o,c] X[b,c,n]) * cs[b,n] + bias[o] )
// EPI: 0 = none, 1 = SiLU, 2 = + skip[b,o,n]*(*sscale), 3 = add into Y (Y += acc + bias)
template <int EPI, bool GAMMA, bool CS>
__global__ void __launch_bounds__(256) mm_kernel(
    const float* __restrict__ W, const float* __restrict__ gamma,
    const float* __restrict__ bias, const float* __restrict__ X,
    const float* __restrict__ colscale, const float* __restrict__ skip,
    const float* __restrict__ sscale, float* __restrict__ Y,
    int O, int N)
{
    __shared__ float Ws[16][68];
    __shared__ float Xs[16][68];
    const int b  = blockIdx.z;
    const int o0 = blockIdx.y * 64, n0 = blockIdx.x * 64;
    const float* Xb = X + (size_t)b * C_ * N;
    float* Yb = Y + (size_t)b * O * N;
    const int tid = threadIdx.x;
    const int ty = tid >> 4, tx = tid & 15;

    u64 acc[4][2];
#pragma unroll
    for (int r = 0; r < 4; r++) { acc[r][0] = 0ull; acc[r][1] = 0ull; }

    const int wm = tid >> 2, wq = tid & 3;   // W tile: 64 rows x 16 k, float4 per thread
    const int xk = tid >> 4, xq = tid & 15;  // X tile: 16 k x 64 n, float4 per thread

    for (int c0 = 0; c0 < C_; c0 += 16) {
        float4 wv = *(const float4*)&W[(size_t)(o0 + wm) * C_ + c0 + wq * 4];
        if (GAMMA) {
            wv.x *= gamma[c0 + wq * 4 + 0];
            wv.y *= gamma[c0 + wq * 4 + 1];
            wv.z *= gamma[c0 + wq * 4 + 2];
            wv.w *= gamma[c0 + wq * 4 + 3];
        }
        float4 xv = *(const float4*)&Xb[(size_t)(c0 + xk) * N + n0 + xq * 4];
        Ws[wq * 4 + 0][wm] = wv.x;
        Ws[wq * 4 + 1][wm] = wv.y;
        Ws[wq * 4 + 2][wm] = wv.z;
        Ws[wq * 4 + 3][wm] = wv.w;
        *(float4*)&Xs[xk][xq * 4] = xv;
        __syncthreads();
#pragma unroll
        for (int kk = 0; kk < 16; kk++) {
            float4 av = *(const float4*)&Ws[kk][ty * 4];
            float4 bv = *(const float4*)&Xs[kk][tx * 4];
            u64 b0 = pk2(bv.x, bv.y), b1 = pk2(bv.z, bv.w);
            u64 a0 = pk2(av.x, av.x); fma2(acc[0][0], a0, b0); fma2(acc[0][1], a0, b1);
            u64 a1 = pk2(av.y, av.y); fma2(acc[1][0], a1, b0); fma2(acc[1][1], a1, b1);
            u64 a2 = pk2(av.z, av.z); fma2(acc[2][0], a2, b0); fma2(acc[2][1], a2, b1);
            u64 a3 = pk2(av.w, av.w); fma2(acc[3][0], a3, b0); fma2(acc[3][1], a3, b1);
        }
        __syncthreads();
    }

    const float* csb = CS ? (colscale + (size_t)b * N) : nullptr;
    float qssv = 0.f;
    if (EPI == 2) qssv = *sscale;
    const float* skipb = (EPI == 2) ? (skip + (size_t)b * C_ * N) : nullptr;

#pragma unroll
    for (int r = 0; r < 4; r++) {
        int o = o0 + ty * 4 + r;
        float bo = bias[o];
        float v0, v1, v2, v3;
        up2(acc[r][0], v0, v1);
        up2(acc[r][1], v2, v3);
        float vv[4] = {v0, v1, v2, v3};
        float* py = &Yb[(size_t)o * N + n0 + tx * 4];
        float4 ov;
#pragma unroll
        for (int j = 0; j < 4; j++) {
            float x = vv[j];
            if (CS) x *= csb[n0 + tx * 4 + j];
            x += bo;
            if (EPI == 1) x = x / (1.f + expf(-x));
            if (EPI == 2) x += skipb[(size_t)o * N + n0 + tx * 4 + j] * qssv;
            if (EPI == 3) x += py[j];
            (&ov.x)[j] = x;
        }
        *(float4*)py = ov;
    }
}

// ---------------- gated SiLU: u[b,c,n] = t1[b,c,n] * silu(t1[b,c+C,n]) ----------------
__global__ void glu_kernel(const float* __restrict__ T1, float* __restrict__ U, int N) {
    int b = blockIdx.z, c = blockIdx.y;
    int n = blockIdx.x * 256 + threadIdx.x;
    size_t base = (size_t)b * 2 * C_ * N;
    float a = T1[base + (size_t)c * N + n];
    float g = T1[base + (size_t)(c + C_) * N + n];
    U[((size_t)b * C_ + c) * N + n] = a * (g / (1.f + expf(-g)));
}

// ---------------- per-frame cross attention: one block per (b,t) ----------------
// smem: ks[128][64], vst[64][132] (V transposed, padded), qs[128][64], pst[64][68]
__global__ void __launch_bounds__(256) attn_kernel(
    const float* __restrict__ Q, const float* __restrict__ Kp, const float* __restrict__ Vp,
    const float* __restrict__ basis, const float* __restrict__ p_ss, const float* __restrict__ p_ps,
    float* __restrict__ Att)
{
    extern __shared__ float sm[];
    float* ks  = sm;                   // [128][64]
    float* vst = ks + 128 * 64;        // [64][132]  vst[k][c]
    float* qs  = vst + 64 * 132;       // [128][64]
    float* pst = qs + 128 * 64;        // [64][68]   pst[k][f_local]
    const int t = blockIdx.x, b = blockIdx.y;
    const int tid = threadIdx.x;
    const int ty = tid >> 4, tx = tid & 15;
    const float ss = *p_ss, prs = *p_ps;

    for (int idx = tid; idx < C_ * K_; idx += 256) {
        int c = idx >> 6, kk = idx & 63;
        size_t g = (((size_t)b * C_ + c) * T_ + t) * K_ + kk;
        ks[c * 64 + kk]   = Kp[g];
        vst[kk * 132 + c] = Vp[g];
    }
    __syncthreads();

    for (int f0 = 0; f0 < F_; f0 += 64) {
        for (int idx = tid; idx < C_ * 64; idx += 256) {
            int c = idx >> 6, fl = idx & 63;
            qs[c * 64 + fl] = Q[(((size_t)b * C_ + c) * T_ + t) * F_ + f0 + fl];
        }
        __syncthreads();

        // S[f=ty*4+r][k=tx*4+j] = sum_c qs[c][f] * ks[c][k]
        u64 acc[4][2];
#pragma unroll
        for (int r = 0; r < 4; r++) { acc[r][0] = 0ull; acc[r][1] = 0ull; }
#pragma unroll 8
        for (int c = 0; c < C_; c++) {
            float4 av = *(const float4*)&qs[c * 64 + ty * 4];
            float4 bv = *(const float4*)&ks[c * 64 + tx * 4];
            u64 b0 = pk2(bv.x, bv.y), b1 = pk2(bv.z, bv.w);
            u64 a0 = pk2(av.x, av.x); fma2(acc[0][0], a0, b0); fma2(acc[0][1], a0, b1);
            u64 a1 = pk2(av.y, av.y); fma2(acc[1][0], a1, b0); fma2(acc[1][1], a1, b1);
            u64 a2 = pk2(av.z, av.z); fma2(acc[2][0], a2, b0); fma2(acc[2][1], a2, b1);
            u64 a3 = pk2(av.w, av.w); fma2(acc[3][0], a3, b0); fma2(acc[3][1], a3, b1);
        }

        // scale + band prior + softmax over k (row spans tx group of 16 threads)
#pragma unroll
        for (int r = 0; r < 4; r++) {
            float s0, s1, s2, s3;
            up2(acc[r][0], s0, s1);
            up2(acc[r][1], s2, s3);
            int f = f0 + ty * 4 + r;
            s0 = fmaf(s0, ss, basis[(tx * 4 + 0) * F_ + f] * prs);
            s1 = fmaf(s1, ss, basis[(tx * 4 + 1) * F_ + f] * prs);
            s2 = fmaf(s2, ss, basis[(tx * 4 + 2) * F_ + f] * prs);
            s3 = fmaf(s3, ss, basis[(tx * 4 + 3) * F_ + f] * prs);
            float m = fmaxf(fmaxf(s0, s1), fmaxf(s2, s3));
            m = fmaxf(m, __shfl_xor_sync(0xffffffffu, m, 1));
            m = fmaxf(m, __shfl_xor_sync(0xffffffffu, m, 2));
            m = fmaxf(m, __shfl_xor_sync(0xffffffffu, m, 4));
            m = fmaxf(m, __shfl_xor_sync(0xffffffffu, m, 8));
            float e0 = __expf(s0 - m), e1 = __expf(s1 - m);
            float e2 = __expf(s2 - m), e3 = __expf(s3 - m);
            float sum = (e0 + e1) + (e2 + e3);
            sum += __shfl_xor_sync(0xffffffffu, sum, 1);
            sum += __shfl_xor_sync(0xffffffffu, sum, 2);
            sum += __shfl_xor_sync(0xffffffffu, sum, 4);
            sum += __shfl_xor_sync(0xffffffffu, sum, 8);
            float rs = 1.f / sum;
            int fl = ty * 4 + r;
            pst[(tx * 4 + 0) * 68 + fl] = e0 * rs;
            pst[(tx * 4 + 1) * 68 + fl] = e1 * rs;
            pst[(tx * 4 + 2) * 68 + fl] = e2 * rs;
            pst[(tx * 4 + 3) * 68 + fl] = e3 * rs;
        }
        __syncthreads();

        // att[c=ty*8+r][fl=tx*4+j] = sum_k vst[k][c] * pst[k][fl]
        u64 acc2[8][2];
#pragma unroll
        for (int r = 0; r < 8; r++) { acc2[r][0] = 0ull; acc2[r][1] = 0ull; }
#pragma unroll 4
        for (int kk = 0; kk < K_; kk++) {
            float4 bv = *(const float4*)&pst[kk * 68 + tx * 4];
            u64 b0 = pk2(bv.x, bv.y), b1 = pk2(bv.z, bv.w);
            const float* vr = &vst[kk * 132 + ty * 8];
#pragma unroll
            for (int r = 0; r < 8; r++) {
                u64 ar = pk2(vr[r], vr[r]);
                fma2(acc2[r][0], ar, b0);
                fma2(acc2[r][1], ar, b1);
            }
        }
#pragma unroll
        for (int r = 0; r < 8; r++) {
            int c = ty * 8 + r;
            float v0, v1, v2, v3;
            up2(acc2[r][0], v0, v1);
            up2(acc2[r][1], v2, v3);
            *(float4*)&Att[(((size_t)b * C_ + c) * T_ + t) * F_ + f0 + tx * 4] =
                make_float4(v0, v1, v2, v3);
        }
        __syncthreads();
    }
}

// ---------------- launch ----------------
extern "C" void kernel_launch(void* const* d_in, const int* in_sizes, int n_in,
                              void* d_out, int out_size)
{
    const float* latent     = (const float*)d_in[0];
    const float* side       = (const float*)d_in[1];
    const float* basis      = (const float*)d_in[2];
    const float* lp_gamma   = (const float*)d_in[3];
    const float* lp_w       = (const float*)d_in[4];
    const float* lp_b       = (const float*)d_in[5];
    const float* qn_gamma   = (const float*)d_in[6];
    const float* qmlp_in_w  = (const float*)d_in[7];
    const float* qmlp_in_b  = (const float*)d_in[8];
    const float* qmlp_out_w = (const float*)d_in[9];
    const float* qmlp_out_b = (const float*)d_in[10];
    const float* q_w        = (const float*)d_in[11];
    const float* q_b        = (const float*)d_in[12];
    const float* k_w        = (const float*)d_in[13];
    const float* k_b        = (const float*)d_in[14];
    const float* v_w        = (const float*)d_in[15];
    const float* v_b        = (const float*)d_in[16];
    const float* o_w        = (const float*)d_in[17];
    const float* o_b        = (const float*)d_in[18];
    const float* ffn_gamma  = (const float*)d_in[19];
    const float* ffn_in_w   = (const float*)d_in[20];
    const float* ffn_in_b   = (const float*)d_in[21];
    const float* ffn_out_w  = (const float*)d_in[22];
    const float* ffn_out_b  = (const float*)d_in[23];
    const float* score_scale= (const float*)d_in[24];
    const float* prior_scale= (const float*)d_in[25];
    const float* qss        = (const float*)d_in[26];
    float* out = (float*)d_out;

    void* p;
    cudaGetSymbolAddress(&p, g_lat_h); float* lat_h = (float*)p;
    cudaGetSymbolAddress(&p, g_kbuf);  float* kb    = (float*)p;
    cudaGetSymbolAddress(&p, g_vbuf);  float* vb    = (float*)p;
    cudaGetSymbolAddress(&p, g_t1);    float* t1    = (float*)p;
    cudaGetSymbolAddress(&p, g_u);     float* u     = (float*)p;
    cudaGetSymbolAddress(&p, g_qh);    float* qh    = (float*)p;
    cudaGetSymbolAddress(&p, g_qb);    float* qb    = (float*)p;
    cudaGetSymbolAddress(&p, g_att);   float* att   = (float*)p;
    cudaGetSymbolAddress(&p, g_invl);  float* invl  = (float*)p;
    cudaGetSymbolAddress(&p, g_invs);  float* invs  = (float*)p;

    // ---- latent path: latent_h = silu(lp_w@rmsnorm(latent)+lp_b); k,v projections
    rmsinv_kernel<<<dim3(NL / 256, B_), 256>>>(latent, invl, NL);
    mm_kernel<1, true, true><<<dim3(NL / 64, 2, B_), 256>>>(
        lp_w, lp_gamma, lp_b, latent, invl, nullptr, nullptr, lat_h, C_, NL);
    mm_kernel<0, false, false><<<dim3(NL / 64, 2, B_), 256>>>(
        k_w, nullptr, k_b, lat_h, nullptr, nullptr, nullptr, kb, C_, NL);
    mm_kernel<0, false, false><<<dim3(NL / 64, 2, B_), 256>>>(
        v_w, nullptr, v_b, lat_h, nullptr, nullptr, nullptr, vb, C_, NL);

    // ---- side path: query_h = swiglu(rmsnorm(side)); q projection
    rmsinv_kernel<<<dim3(NS / 256, B_), 256>>>(side, invs, NS);
    mm_kernel<0, true, true><<<dim3(NS / 64, 4, B_), 256>>>(
        qmlp_in_w, qn_gamma, qmlp_in_b, side, invs, nullptr, nullptr, t1, 2 * C_, NS);
    glu_kernel<<<dim3(NS / 256, C_, B_), 256>>>(t1, u, NS);
    mm_kernel<0, false, false><<<dim3(NS / 64, 2, B_), 256>>>(
        qmlp_out_w, nullptr, qmlp_out_b, u, nullptr, nullptr, nullptr, qh, C_, NS);
    mm_kernel<0, false, false><<<dim3(NS / 64, 2, B_), 256>>>(
        q_w, nullptr, q_b, qh, nullptr, nullptr, nullptr, qb, C_, NS);

    // ---- attention (per-frame) -> attended
    constexpr int ATTN_SMEM = (128 * 64 + 64 * 132 + 128 * 64 + 64 * 68) * 4;  // 116736
    cudaFuncSetAttribute(attn_kernel, cudaFuncAttributeMaxDynamicSharedMemorySize, ATTN_SMEM);
    attn_kernel<<<dim3(T_, B_), 256, ATTN_SMEM>>>(qb, kb, vb, basis, score_scale, prior_scale, att);

    // ---- hidden = o_w@attended + o_b + query_h * query_skip_scale
    mm_kernel<2, false, false><<<dim3(NS / 64, 2, B_), 256>>>(
        o_w, nullptr, o_b, att, nullptr, qh, qss, out, C_, NS);

    // ---- ffn: hidden += swiglu(rmsnorm(hidden))
    rmsinv_kernel<<<dim3(NS / 256, B_), 256>>>(out, invs, NS);
    mm_kernel<0, true, true><<<dim3(NS / 64, 4, B_), 256>>>(
        ffn_in_w, ffn_gamma, ffn_in_b, out, invs, nullptr, nullptr, t1, 2 * C_, NS);
    glu_kernel<<<dim3(NS / 256, C_, B_), 256>>>(t1, u, NS);
    mm_kernel<3, false, false><<<dim3(NS / 64, 2, B_), 256>>>(
        ffn_out_w, nullptr, ffn_out_b, u, nullptr, nullptr, nullptr, out, C_, NS);
}

// round 5
// speedup vs baseline: 1.2086x; 1.2070x over previous
#include <cuda_runtime.h>
#include <cuda_bf16.h>
#include <math.h>
#include <stdint.h>

namespace {
constexpr int C_ = 128;
constexpr int B_ = 8;
constexpr int T_ = 128;
constexpr int F_ = 512;
constexpr int K_ = 64;
constexpr int NL = T_ * K_;   // 8192
constexpr int NS = T_ * F_;   // 65536
}

// ---------------- scratch (device globals; no allocation allowed) ----------------
__device__ float g_lat_h[(size_t)B_ * C_ * NL];
__device__ float g_kbuf [(size_t)B_ * C_ * NL];
__device__ float g_vbuf [(size_t)B_ * C_ * NL];
__device__ float g_u  [(size_t)B_ * C_ * NS];
__device__ float g_qh [(size_t)B_ * C_ * NS];
__device__ float g_qb [(size_t)B_ * C_ * NS];
__device__ float g_att[(size_t)B_ * C_ * NS];
__device__ __align__(16) __nv_bfloat16 g_whi[11 * 16384];
__device__ __align__(16) __nv_bfloat16 g_wlo[11 * 16384];

namespace {
// weight offsets in g_whi/g_wlo (elements)
constexpr int WO_LP = 0, WO_QMI = 16384, WO_QMO = 49152, WO_Q = 65536,
              WO_K = 81920, WO_V = 98304, WO_O = 114688, WO_FFI = 131072, WO_FFO = 163840;

// smem tile pitch (bf16 elements): 136*2 = 272 bytes -> rows rotate 16B mod 128B,
// ldmatrix 8-row phases hit 8 distinct 16B banks (conflict-free, no swizzle needed)
constexpr int PB = 136;

// SMEM layout (bytes)
constexpr int OFF_AH   = 0;          // 34816  A hi  [128][PB]
constexpr int OFF_AL   = 34816;      // 34816  A lo
constexpr int OFF_BH   = 69632;      // 34816  B hi  [k=128][PB] (n contiguous)
constexpr int OFF_BL   = 104448;     // 34816  B lo
constexpr int OFF_XS   = 139264;     // 65536  fp32 staging (RMS only)
constexpr int OFF_PART = 204800;     // 4096   8 warps x 128 col partials
constexpr int OFF_INV  = 208896;     // 512    inv[128]
constexpr int SMEM_RMS   = 209408;
constexpr int SMEM_PLAIN = 139264;
}

__device__ __forceinline__ uint32_t smem_u32(const void* p) {
    uint32_t a;
    asm("{ .reg .u64 t; cvta.to.shared.u64 t, %1; cvt.u32.u64 %0, t; }" : "=r"(a) : "l"(p));
    return a;
}

#define LDSM4(r, addr) \
    asm volatile("ldmatrix.sync.aligned.m8n8.x4.shared.b16 {%0,%1,%2,%3}, [%4];" \
        : "=r"((r)[0]), "=r"((r)[1]), "=r"((r)[2]), "=r"((r)[3]) : "r"(addr))
#define LDSM4T(r, addr) \
    asm volatile("ldmatrix.sync.aligned.m8n8.x4.trans.shared.b16 {%0,%1,%2,%3}, [%4];" \
        : "=r"((r)[0]), "=r"((r)[1]), "=r"((r)[2]), "=r"((r)[3]) : "r"(addr))

__device__ __forceinline__ void mma16816(float* d, const uint32_t* a, uint32_t b0, uint32_t b1) {
    asm volatile("mma.sync.aligned.m16n8k16.row.col.f32.bf16.bf16.f32 "
        "{%0,%1,%2,%3},{%4,%5,%6,%7},{%8,%9},{%0,%1,%2,%3};"
        : "+f"(d[0]), "+f"(d[1]), "+f"(d[2]), "+f"(d[3])
        : "r"(a[0]), "r"(a[1]), "r"(a[2]), "r"(a[3]), "r"(b0), "r"(b1));
}

// ---------------- weight prep: gamma-folded bf16 hi/lo split ----------------
__global__ void wprep(const float* __restrict__ W, const float* __restrict__ gamma,
                      __nv_bfloat16* __restrict__ hi, __nv_bfloat16* __restrict__ lo, int n) {
    int i = blockIdx.x * 256 + threadIdx.x;
    if (i >= n) return;
    float v = W[i];
    if (gamma) v *= gamma[i & (C_ - 1)];
    __nv_bfloat16 h = __float2bfloat16(v);
    hi[i] = h;
    lo[i] = __float2bfloat16(v - __bfloat162float(h));
}

__device__ __forceinline__ void cvt4store(float4 v, __nv_bfloat16* ph, __nv_bfloat16* pl) {
    __align__(8) __nv_bfloat16 h[4], l[4];
    float f[4] = {v.x, v.y, v.z, v.w};
#pragma unroll
    for (int j = 0; j < 4; j++) {
        __nv_bfloat16 hb = __float2bfloat16(f[j]);
        h[j] = hb;
        l[j] = __float2bfloat16(f[j] - __bfloat162float(hb));
    }
    *(uint2*)ph = *(uint2*)h;
    *(uint2*)pl = *(uint2*)l;
}

// ---------------- HMMA GEMM over tile M=128, N=128, K=128 ----------------
// EPI: 0 none, 1 silu, 2 swiglu (a/g rows interleaved), 3 +skip*sscale, 4 accumulate into Y
template <int EPI, bool RMS>
__global__ void __launch_bounds__(256, 1) gemm_mma(
    const __nv_bfloat16* __restrict__ Whi, const __nv_bfloat16* __restrict__ Wlo,
    const float* __restrict__ bias, const float* __restrict__ X,
    const float* __restrict__ skip, const float* __restrict__ sscale,
    float* __restrict__ Y, int N)
{
    extern __shared__ __align__(16) char sm[];
    const int tid = threadIdx.x, wid = tid >> 5, lane = tid & 31;
    const int b = blockIdx.z, n0 = blockIdx.x * 128;
    __nv_bfloat16* Ah = (__nv_bfloat16*)(sm + OFF_AH);
    __nv_bfloat16* Al = (__nv_bfloat16*)(sm + OFF_AL);
    __nv_bfloat16* Bh = (__nv_bfloat16*)(sm + OFF_BH);
    __nv_bfloat16* Bl = (__nv_bfloat16*)(sm + OFF_BL);

    // ---- A (weights) 128x128 bf16 hi/lo -> smem pitch PB
    {
        const int r = tid >> 1;             // mma row 0..127
        const int h = (tid & 1) * 64;       // col half
        int wrow;
        if (EPI == 2) {
            int ch = blockIdx.y * 64 + (r >> 1);
            wrow = (r & 1) ? (C_ + ch) : ch;   // even mma row = a, odd = g
        } else {
            wrow = r;
        }
        const uint4* sh = (const uint4*)(Whi + (size_t)wrow * C_ + h);
        const uint4* sl = (const uint4*)(Wlo + (size_t)wrow * C_ + h);
        uint4* dh = (uint4*)(Ah + r * PB + h);
        uint4* dl = (uint4*)(Al + r * PB + h);
#pragma unroll
        for (int i = 0; i < 8; i++) { dh[i] = sh[i]; dl[i] = sl[i]; }
    }

    // ---- B (activations) [c=128][n=128] fp32 -> bf16 hi/lo, optional fused RMSNorm
    const float* Xb = X + (size_t)b * C_ * N + n0;
    if (RMS) {
        float* Xs = (float*)(sm + OFF_XS);
        float* part = (float*)(sm + OFF_PART);
        float* inv = (float*)(sm + OFF_INV);
        float sq0 = 0.f, sq1 = 0.f, sq2 = 0.f, sq3 = 0.f;
#pragma unroll 4
        for (int c = wid; c < C_; c += 8) {
            float4 v = *(const float4*)(Xb + (size_t)c * N + lane * 4);
            *(float4*)(Xs + c * 128 + lane * 4) = v;
            sq0 = fmaf(v.x, v.x, sq0); sq1 = fmaf(v.y, v.y, sq1);
            sq2 = fmaf(v.z, v.z, sq2); sq3 = fmaf(v.w, v.w, sq3);
        }
        part[wid * 128 + lane * 4 + 0] = sq0;
        part[wid * 128 + lane * 4 + 1] = sq1;
        part[wid * 128 + lane * 4 + 2] = sq2;
        part[wid * 128 + lane * 4 + 3] = sq3;
        __syncthreads();
        if (tid < 128) {
            float s = 0.f;
#pragma unroll
            for (int w = 0; w < 8; w++) s += part[w * 128 + tid];
            inv[tid] = rsqrtf(s * (1.0f / 128.0f) + 1e-6f);
        }
        __syncthreads();
        const int c = tid >> 1, nb = (tid & 1) * 64;
#pragma unroll
        for (int i = 0; i < 16; i++) {
            float4 v = *(const float4*)(Xs + c * 128 + nb + i * 4);
            float4 iv = *(const float4*)(inv + nb + i * 4);
            v.x *= iv.x; v.y *= iv.y; v.z *= iv.z; v.w *= iv.w;
            cvt4store(v, Bh + c * PB + nb + i * 4, Bl + c * PB + nb + i * 4);
        }
    } else {
        const int c = tid >> 1, nb = (tid & 1) * 64;
        const float* src = Xb + (size_t)c * N + nb;
#pragma unroll
        for (int i = 0; i < 16; i++) {
            float4 v = *(const float4*)(src + i * 4);
            cvt4store(v, Bh + c * PB + nb + i * 4, Bl + c * PB + nb + i * 4);
        }
    }
    __syncthreads();

    // ---- mainloop: 3 split passes x 8 k-steps, 16 HMMA each
    const int wm = (wid & 3) * 32, wn = (wid >> 2) * 64;
    float acc[2][8][4];
#pragma unroll
    for (int mf = 0; mf < 2; mf++)
#pragma unroll
        for (int nb = 0; nb < 8; nb++)
#pragma unroll
            for (int j = 0; j < 4; j++) acc[mf][nb][j] = 0.f;

    const uint32_t sb = smem_u32(sm);
    const uint32_t aOff = ((wm + (lane & 15)) * PB + (lane >> 4) * 8) * 2;
    const uint32_t bOff = ((lane & 15) * PB + wn + (lane >> 4) * 8) * 2;

#pragma unroll
    for (int pass = 0; pass < 3; pass++) {
        const uint32_t aTile = sb + (pass == 2 ? OFF_AL : OFF_AH) + aOff;
        const uint32_t bTile = sb + (pass == 1 ? OFF_BL : OFF_BH) + bOff;
#pragma unroll
        for (int ks = 0; ks < 8; ks++) {
            uint32_t a0[4], a1[4], bf[4][4];
            LDSM4(a0, aTile + ks * 32);
            LDSM4(a1, aTile + 16 * PB * 2 + ks * 32);
#pragma unroll
            for (int n2 = 0; n2 < 4; n2++)
                LDSM4T(bf[n2], bTile + ks * 16 * PB * 2 + n2 * 32);
#pragma unroll
            for (int n2 = 0; n2 < 4; n2++) {
                mma16816(acc[0][n2 * 2 + 0], a0, bf[n2][0], bf[n2][1]);
                mma16816(acc[0][n2 * 2 + 1], a0, bf[n2][2], bf[n2][3]);
                mma16816(acc[1][n2 * 2 + 0], a1, bf[n2][0], bf[n2][1]);
                mma16816(acc[1][n2 * 2 + 1], a1, bf[n2][2], bf[n2][3]);
            }
        }
    }

    // ---- epilogue. frag map: d0,d1 -> row g=lane>>2, cols q*2,q*2+1; d2,d3 -> row g+8
    const int g = lane >> 2, q = lane & 3;
    if (EPI == 2) {
        // even mma row = a(ch), odd = g(ch); pair rows (2j,2j+1) = lanes (l, l+4)
        const int chBase = blockIdx.y * 64 + (wm >> 1);
#pragma unroll
        for (int mf = 0; mf < 2; mf++) {
            const int ch = chBase + mf * 8 + (g >> 1);   // valid when g even
            float ba0 = bias[ch], bg0 = bias[C_ + ch];
            float ba1 = bias[ch + 4], bg1 = bias[C_ + ch + 4];
#pragma unroll
            for (int nb = 0; nb < 8; nb++) {
                float* d = acc[mf][nb];
                float gt0 = __shfl_down_sync(0xffffffffu, d[0], 4);
                float gt1 = __shfl_down_sync(0xffffffffu, d[1], 4);
                float gt2 = __shfl_down_sync(0xffffffffu, d[2], 4);
                float gt3 = __shfl_down_sync(0xffffffffu, d[3], 4);
                if (!(g & 1)) {
                    float a0 = d[0] + ba0, a1 = d[1] + ba0;
                    float g0 = gt0 + bg0, g1 = gt1 + bg0;
                    float a2 = d[2] + ba1, a3 = d[3] + ba1;
                    float g2 = gt2 + bg1, g3 = gt3 + bg1;
                    float o0 = a0 * (g0 / (1.f + __expf(-g0)));
                    float o1 = a1 * (g1 / (1.f + __expf(-g1)));
                    float o2 = a2 * (g2 / (1.f + __expf(-g2)));
                    float o3 = a3 * (g3 / (1.f + __expf(-g3)));
                    int col = n0 + wn + nb * 8 + q * 2;
                    *(float2*)(Y + ((size_t)b * C_ + ch) * N + col) = make_float2(o0, o1);
                    *(float2*)(Y + ((size_t)b * C_ + ch + 4) * N + col) = make_float2(o2, o3);
                }
            }
        }
    } else {
        const float sv = (EPI == 3) ? *sscale : 0.f;
#pragma unroll
        for (int mf = 0; mf < 2; mf++) {
            const int r0 = wm + mf * 16 + g;
            const float bo0 = bias[r0], bo1 = bias[r0 + 8];
            float* y0 = Y + ((size_t)b * C_ + r0) * N + n0 + wn;
            float* y1 = Y + ((size_t)b * C_ + r0 + 8) * N + n0 + wn;
            const float* s0 = (EPI == 3) ? (skip + ((size_t)b * C_ + r0) * N + n0 + wn) : nullptr;
            const float* s1 = (EPI == 3) ? (skip + ((size_t)b * C_ + r0 + 8) * N + n0 + wn) : nullptr;
#pragma unroll
            for (int nb = 0; nb < 8; nb++) {
                float* d = acc[mf][nb];
                int col = nb * 8 + q * 2;
                float o0 = d[0] + bo0, o1 = d[1] + bo0;
                float o2 = d[2] + bo1, o3 = d[3] + bo1;
                if (EPI == 1) {
                    o0 = o0 / (1.f + __expf(-o0));
                    o1 = o1 / (1.f + __expf(-o1));
                    o2 = o2 / (1.f + __expf(-o2));
                    o3 = o3 / (1.f + __expf(-o3));
                }
                if (EPI == 3) {
                    float2 k0 = *(const float2*)(s0 + col);
                    float2 k1 = *(const float2*)(s1 + col);
                    o0 += k0.x * sv; o1 += k0.y * sv;
                    o2 += k1.x * sv; o3 += k1.y * sv;
                }
                if (EPI == 4) {
                    float2 k0 = *(const float2*)(y0 + col);
                    float2 k1 = *(const float2*)(y1 + col);
                    o0 += k0.x; o1 += k0.y;
                    o2 += k1.x; o3 += k1.y;
                }
                *(float2*)(y0 + col) = make_float2(o0, o1);
                *(float2*)(y1 + col) = make_float2(o2, o3);
            }
        }
    }
}

// ---------------- packed fp32x2 helpers (SIMT attention) ----------------
typedef unsigned long long u64;
__device__ __forceinline__ u64 pk2(float x, float y) {
    u64 r; asm("mov.b64 %0,{%1,%2};" : "=l"(r) : "f"(x), "f"(y)); return r;
}
__device__ __forceinline__ void up2(u64 v, float& x, float& y) {
    asm("mov.b64 {%0,%1},%2;" : "=f"(x), "=f"(y) : "l"(v));
}
__device__ __forceinline__ void fma2(u64& c, u64 a, u64 b) {
    asm("fma.rn.f32x2 %0,%1,%2,%0;" : "+l"(c) : "l"(a), "l"(b));
}

// ---------------- per-frame cross attention: one block per (b,t) ----------------
__global__ void __launch_bounds__(256) attn_kernel(
    const float* __restrict__ Q, const float* __restrict__ Kp, const float* __restrict__ Vp,
    const float* __restrict__ basis, const float* __restrict__ p_ss, const float* __restrict__ p_ps,
    float* __restrict__ Att)
{
    extern __shared__ float smf[];
    float* ks  = smf;                  // [128][64]
    float* vst = ks + 128 * 64;        // [64][132]
    float* qs  = vst + 64 * 132;       // [128][64]
    float* pst = qs + 128 * 64;        // [64][68]
    const int t = blockIdx.x, b = blockIdx.y;
    const int tid = threadIdx.x;
    const int ty = tid >> 4, tx = tid & 15;
    const float ss = *p_ss, prs = *p_ps;

    for (int idx = tid; idx < C_ * K_; idx += 256) {
        int c = idx >> 6, kk = idx & 63;
        size_t g = (((size_t)b * C_ + c) * T_ + t) * K_ + kk;
        ks[c * 64 + kk]   = Kp[g];
        vst[kk * 132 + c] = Vp[g];
    }
    __syncthreads();

    for (int f0 = 0; f0 < F_; f0 += 64) {
        for (int idx = tid; idx < C_ * 64; idx += 256) {
            int c = idx >> 6, fl = idx & 63;
            qs[c * 64 + fl] = Q[(((size_t)b * C_ + c) * T_ + t) * F_ + f0 + fl];
        }
        __syncthreads();

        u64 acc[4][2];
#pragma unroll
        for (int r = 0; r < 4; r++) { acc[r][0] = 0ull; acc[r][1] = 0ull; }
#pragma unroll 8
        for (int c = 0; c < C_; c++) {
            float4 av = *(const float4*)&qs[c * 64 + ty * 4];
            float4 bv = *(const float4*)&ks[c * 64 + tx * 4];
            u64 b0 = pk2(bv.x, bv.y), b1 = pk2(bv.z, bv.w);
            u64 a0 = pk2(av.x, av.x); fma2(acc[0][0], a0, b0); fma2(acc[0][1], a0, b1);
            u64 a1 = pk2(av.y, av.y); fma2(acc[1][0], a1, b0); fma2(acc[1][1], a1, b1);
            u64 a2 = pk2(av.z, av.z); fma2(acc[2][0], a2, b0); fma2(acc[2][1], a2, b1);
            u64 a3 = pk2(av.w, av.w); fma2(acc[3][0], a3, b0); fma2(acc[3][1], a3, b1);
        }

#pragma unroll
        for (int r = 0; r < 4; r++) {
            float s0, s1, s2, s3;
            up2(acc[r][0], s0, s1);
            up2(acc[r][1], s2, s3);
            int f = f0 + ty * 4 + r;
            s0 = fmaf(s0, ss, basis[(tx * 4 + 0) * F_ + f] * prs);
            s1 = fmaf(s1, ss, basis[(tx * 4 + 1) * F_ + f] * prs);
            s2 = fmaf(s2, ss, basis[(tx * 4 + 2) * F_ + f] * prs);
            s3 = fmaf(s3, ss, basis[(tx * 4 + 3) * F_ + f] * prs);
            float m = fmaxf(fmaxf(s0, s1), fmaxf(s2, s3));
            m = fmaxf(m, __shfl_xor_sync(0xffffffffu, m, 1));
            m = fmaxf(m, __shfl_xor_sync(0xffffffffu, m, 2));
            m = fmaxf(m, __shfl_xor_sync(0xffffffffu, m, 4));
            m = fmaxf(m, __shfl_xor_sync(0xffffffffu, m, 8));
            float e0 = __expf(s0 - m), e1 = __expf(s1 - m);
            float e2 = __expf(s2 - m), e3 = __expf(s3 - m);
            float sum = (e0 + e1) + (e2 + e3);
            sum += __shfl_xor_sync(0xffffffffu, sum, 1);
            sum += __shfl_xor_sync(0xffffffffu, sum, 2);
            sum += __shfl_xor_sync(0xffffffffu, sum, 4);
            sum += __shfl_xor_sync(0xffffffffu, sum, 8);
            float rs = 1.f / sum;
            int fl = ty * 4 + r;
            pst[(tx * 4 + 0) * 68 + fl] = e0 * rs;
            pst[(tx * 4 + 1) * 68 + fl] = e1 * rs;
            pst[(tx * 4 + 2) * 68 + fl] = e2 * rs;
            pst[(tx * 4 + 3) * 68 + fl] = e3 * rs;
        }
        __syncthreads();

        u64 acc2[8][2];
#pragma unroll
        for (int r = 0; r < 8; r++) { acc2[r][0] = 0ull; acc2[r][1] = 0ull; }
#pragma unroll 4
        for (int kk = 0; kk < K_; kk++) {
            float4 bv = *(const float4*)&pst[kk * 68 + tx * 4];
            u64 b0 = pk2(bv.x, bv.y), b1 = pk2(bv.z, bv.w);
            const float* vr = &vst[kk * 132 + ty * 8];
#pragma unroll
            for (int r = 0; r < 8; r++) {
                u64 ar = pk2(vr[r], vr[r]);
                fma2(acc2[r][0], ar, b0);
                fma2(acc2[r][1], ar, b1);
            }
        }
#pragma unroll
        for (int r = 0; r < 8; r++) {
            int c = ty * 8 + r;
            float v0, v1, v2, v3;
            up2(acc2[r][0], v0, v1);
            up2(acc2[r][1], v2, v3);
            *(float4*)&Att[(((size_t)b * C_ + c) * T_ + t) * F_ + f0 + tx * 4] =
                make_float4(v0, v1, v2, v3);
        }
        __syncthreads();
    }
}

// ---------------- launch ----------------
extern "C" void kernel_launch(void* const* d_in, const int* in_sizes, int n_in,
                              void* d_out, int out_size)
{
    const float* latent     = (const float*)d_in[0];
    const float* side       = (const float*)d_in[1];
    const float* basis      = (const float*)d_in[2];
    const float* lp_gamma   = (const float*)d_in[3];
    const float* lp_w       = (const float*)d_in[4];
    const float* lp_b       = (const float*)d_in[5];
    const float* qn_gamma   = (const float*)d_in[6];
    const float* qmlp_in_w  = (const float*)d_in[7];
    const float* qmlp_in_b  = (const float*)d_in[8];
    const float* qmlp_out_w = (const float*)d_in[9];
    const float* qmlp_out_b = (const float*)d_in[10];
    const float* q_w        = (const float*)d_in[11];
    const float* q_b        = (const float*)d_in[12];
    const float* k_w        = (const float*)d_in[13];
    const float* k_b        = (const float*)d_in[14];
    const float* v_w        = (const float*)d_in[15];
    const float* v_b        = (const float*)d_in[16];
    const float* o_w        = (const float*)d_in[17];
    const float* o_b        = (const float*)d_in[18];
    const float* ffn_gamma  = (const float*)d_in[19];
    const float* ffn_in_w   = (const float*)d_in[20];
    const float* ffn_in_b   = (const float*)d_in[21];
    const float* ffn_out_w  = (const float*)d_in[22];
    const float* ffn_out_b  = (const float*)d_in[23];
    const float* score_scale= (const float*)d_in[24];
    const float* prior_scale= (const float*)d_in[25];
    const float* qss        = (const float*)d_in[26];
    float* out = (float*)d_out;

    void* p;
    cudaGetSymbolAddress(&p, g_lat_h); float* lat_h = (float*)p;
    cudaGetSymbolAddress(&p, g_kbuf);  float* kb    = (float*)p;
    cudaGetSymbolAddress(&p, g_vbuf);  float* vb    = (float*)p;
    cudaGetSymbolAddress(&p, g_u);     float* u     = (float*)p;
    cudaGetSymbolAddress(&p, g_qh);    float* qh    = (float*)p;
    cudaGetSymbolAddress(&p, g_qb);    float* qb    = (float*)p;
    cudaGetSymbolAddress(&p, g_att);   float* att   = (float*)p;
    cudaGetSymbolAddress(&p, g_whi);   __nv_bfloat16* whi = (__nv_bfloat16*)p;
    cudaGetSymbolAddress(&p, g_wlo);   __nv_bfloat16* wlo = (__nv_bfloat16*)p;

    // ---- weight prep (bf16 hi/lo, gamma folded)
    wprep<<<64, 256>>>(lp_w, lp_gamma, whi + WO_LP, wlo + WO_LP, 16384);
    wprep<<<128, 256>>>(qmlp_in_w, qn_gamma, whi + WO_QMI, wlo + WO_QMI, 32768);
    wprep<<<64, 256>>>(qmlp_out_w, nullptr, whi + WO_QMO, wlo + WO_QMO, 16384);
    wprep<<<64, 256>>>(q_w, nullptr, whi + WO_Q, wlo + WO_Q, 16384);
    wprep<<<64, 256>>>(k_w, nullptr, whi + WO_K, wlo + WO_K, 16384);
    wprep<<<64, 256>>>(v_w, nullptr, whi + WO_V, wlo + WO_V, 16384);
    wprep<<<64, 256>>>(o_w, nullptr, whi + WO_O, wlo + WO_O, 16384);
    wprep<<<128, 256>>>(ffn_in_w, ffn_gamma, whi + WO_FFI, wlo + WO_FFI, 32768);
    wprep<<<64, 256>>>(ffn_out_w, nullptr, whi + WO_FFO, wlo + WO_FFO, 16384);

    cudaFuncSetAttribute(gemm_mma<0, false>, cudaFuncAttributeMaxDynamicSharedMemorySize, SMEM_PLAIN);
    cudaFuncSetAttribute(gemm_mma<1, true>,  cudaFuncAttributeMaxDynamicSharedMemorySize, SMEM_RMS);
    cudaFuncSetAttribute(gemm_mma<2, true>,  cudaFuncAttributeMaxDynamicSharedMemorySize, SMEM_RMS);
    cudaFuncSetAttribute(gemm_mma<3, false>, cudaFuncAttributeMaxDynamicSharedMemorySize, SMEM_PLAIN);
    cudaFuncSetAttribute(gemm_mma<4, false>, cudaFuncAttributeMaxDynamicSharedMemorySize, SMEM_PLAIN);

    // ---- latent path: latent_h = silu(lp(rmsnorm(latent))); k, v projections
    gemm_mma<1, true><<<dim3(NL / 128, 1, B_), 256, SMEM_RMS>>>(
        whi + WO_LP, wlo + WO_LP, lp_b, latent, nullptr, nullptr, lat_h, NL);
    gemm_mma<0, false><<<dim3(NL / 128, 1, B_), 256, SMEM_PLAIN>>>(
        whi + WO_K, wlo + WO_K, k_b, lat_h, nullptr, nullptr, kb, NL);
    gemm_mma<0, false><<<dim3(NL / 128, 1, B_), 256, SMEM_PLAIN>>>(
        whi + WO_V, wlo + WO_V, v_b, lat_h, nullptr, nullptr, vb, NL);

    // ---- side path: u = glu(qmlp_in(rmsnorm(side))); qh = qmlp_out(u); qb = q(qh)
    gemm_mma<2, true><<<dim3(NS / 128, 2, B_), 256, SMEM_RMS>>>(
        whi + WO_QMI, wlo + WO_QMI, qmlp_in_b, side, nullptr, nullptr, u, NS);
    gemm_mma<0, false><<<dim3(NS / 128, 1, B_), 256, SMEM_PLAIN>>>(
        whi + WO_QMO, wlo + WO_QMO, qmlp_out_b, u, nullptr, nullptr, qh, NS);
    gemm_mma<0, false><<<dim3(NS / 128, 1, B_), 256, SMEM_PLAIN>>>(
        whi + WO_Q, wlo + WO_Q, q_b, qh, nullptr, nullptr, qb, NS);

    // ---- attention (per-frame) -> attended
    constexpr int ATTN_SMEM = (128 * 64 + 64 * 132 + 128 * 64 + 64 * 68) * 4;  // 116736
    cudaFuncSetAttribute(attn_kernel, cudaFuncAttributeMaxDynamicSharedMemorySize, ATTN_SMEM);
    attn_kernel<<<dim3(T_, B_), 256, ATTN_SMEM>>>(qb, kb, vb, basis, score_scale, prior_scale, att);

    // ---- hidden = o(attended) + o_b + qh * qss
    gemm_mma<3, false><<<dim3(NS / 128, 1, B_), 256, SMEM_PLAIN>>>(
        whi + WO_O, wlo + WO_O, o_b, att, qh, qss, out, NS);

    // ---- ffn: hidden += ffn_out(glu(ffn_in(rmsnorm(hidden))))
    gemm_mma<2, true><<<dim3(NS / 128, 2, B_), 256, SMEM_RMS>>>(
        whi + WO_FFI, wlo + WO_FFI, ffn_in_b, out, nullptr, nullptr, u, NS);
    gemm_mma<4, false><<<dim3(NS / 128, 1, B_), 256, SMEM_PLAIN>>>(
        whi + WO_FFO, wlo + WO_FFO, ffn_out_b, u, nullptr, nullptr, out, NS);
}